// round 7
// baseline (speedup 1.0000x reference)
#include <cuda_runtime.h>
#include <cuda_fp16.h>
#include <cstdint>
#include <math.h>

#define N_ROWS 8192
#define DIMK   1024
#define NCTA   148
#define NJOBS_T 1056         // upper-triangle 128x256 tiles
#define STAGE_BYTES 49152u
#define QS 700.0f

// ---------------- scratch (static device memory, no allocs) ----------------
__device__ __align__(16) float    g_Xn[N_ROWS * DIMK];        // 32 MB normalized fp32
__device__ __align__(16) uint32_t g_Xq[N_ROWS * DIMK / 4];    // 8 MB int8 row-major (packed)
__device__ unsigned long long g_best[N_ROWS];                 // (enc(sim_int)<<32 | ~col)
__device__ float g_logd[N_ROWS];

// ---------------- helpers ----------------
__device__ __forceinline__ uint32_t smem_u32(const void* p) {
    uint32_t a;
    asm("{ .reg .u64 t; cvta.to.shared.u64 t, %1; cvt.u32.u64 %0, t; }" : "=r"(a) : "l"(p));
    return a;
}
__device__ __forceinline__ void cp16(uint32_t dst, const void* src) {
    asm volatile("cp.async.cg.shared.global [%0], [%1], 16;" :: "r"(dst), "l"(src));
}
__device__ __forceinline__ void ldsm4(uint32_t& r0, uint32_t& r1, uint32_t& r2, uint32_t& r3,
                                      uint32_t addr) {
    asm volatile("ldmatrix.sync.aligned.m8n8.x4.shared.b16 {%0,%1,%2,%3}, [%4];"
                 : "=r"(r0), "=r"(r1), "=r"(r2), "=r"(r3) : "r"(addr));
}
// int8 inputs, s32 accumulators, K=32
__device__ __forceinline__ void mma16832i(int* c, uint32_t a0, uint32_t a1, uint32_t a2,
                                          uint32_t a3, uint32_t b0, uint32_t b1) {
    asm volatile("mma.sync.aligned.m16n8k32.row.col.s32.s8.s8.s32 "
                 "{%0,%1,%2,%3}, {%4,%5,%6,%7}, {%8,%9}, {%0,%1,%2,%3};"
                 : "+r"(c[0]), "+r"(c[1]), "+r"(c[2]), "+r"(c[3])
                 : "r"(a0), "r"(a1), "r"(a2), "r"(a3), "r"(b0), "r"(b1));
}
// monotonic s32 -> u32 (flip sign bit)
__device__ __forceinline__ uint32_t ienc(int v) {
    return (uint32_t)v ^ 0x80000000u;
}
__device__ __forceinline__ int q8(float v) {
    const int q = __float2int_rn(v * QS);
    return max(-127, min(127, q));
}
// job index -> (rb, nt); pair u (rb = 2u,2u+1) has 2*(32-u) jobs; S(u) = u*(65-u).
__device__ __forceinline__ uint32_t job_decode(int jj) {
    int u = 0;
    #pragma unroll 1
    while ((u + 1) * (65 - (u + 1)) <= jj) u++;
    const int r = jj - u * (65 - u);
    const int cnt = 32 - u;
    const int rb = 2 * u + (r >= cnt);
    const int nt = u + (r >= cnt ? r - cnt : r);
    return ((uint32_t)rb << 8) | (uint32_t)nt;
}

// ---------------- kernel 1: normalize rows, write fp32 + int8; reset g_best ----------------
__global__ void koleo_normalize_kernel(const float* __restrict__ x) {
    const int row = blockIdx.x;
    const int tid = threadIdx.x;  // 256 threads, 4 elems each
    if (tid == 0) g_best[row] = 0ull;
    const float4 v = ((const float4*)(x + (size_t)row * DIMK))[tid];
    float ss = v.x * v.x + v.y * v.y + v.z * v.z + v.w * v.w;
    #pragma unroll
    for (int o = 16; o; o >>= 1) ss += __shfl_xor_sync(0xFFFFFFFFu, ss, o);
    __shared__ float ws[9];
    if ((tid & 31) == 0) ws[tid >> 5] = ss;
    __syncthreads();
    if (tid == 0) {
        float t = 0.f;
        #pragma unroll
        for (int i = 0; i < 8; i++) t += ws[i];
        ws[8] = 1.f / fmaxf(sqrtf(t), 1e-8f);
    }
    __syncthreads();
    const float s = ws[8];
    float4 y; y.x = v.x * s; y.y = v.y * s; y.z = v.z * s; y.w = v.w * s;
    ((float4*)(g_Xn + (size_t)row * DIMK))[tid] = y;

    const int q0 = q8(y.x), q1 = q8(y.y), q2 = q8(y.z), q3 = q8(y.w);
    const uint32_t packed = (uint32_t)(q0 & 0xFF) | ((uint32_t)(q1 & 0xFF) << 8) |
                            ((uint32_t)(q2 & 0xFF) << 16) | ((uint32_t)(q3 & 0xFF) << 24);
    g_Xq[row * 256 + tid] = packed;
}

// ---------------- kernel 2: persistent int8 GEMM over the upper triangle ----------------
// 148 CTAs; CTA c runs triangle-jobs c, c+148, ... Tile = 128 rows x 256 cols.
// Stage = K-chunk 128 bytes (8 stages/job): A 128x128B (16KB) + B 256x128B (32KB),
// 4 smem buffers, prefetch depth 3, one __syncthreads per stage.
// Swizzle: 16B-chunk idx XOR (row & 7). Both row-side and column-side folds.

__device__ __forceinline__ void copy_stream(uint32_t sbase, const uint32_t* jtab,
                                            int s, int S, int tid) {
    if (s < S) {
        const uint32_t rbnt = jtab[s >> 3];
        const int rb = (int)(rbnt >> 8), nt = (int)(rbnt & 255u), kc = s & 7;
        const uint32_t dst = sbase + (uint32_t)(s & 3) * STAGE_BYTES;
        const uint8_t* gA = (const uint8_t*)g_Xq + (size_t)(rb * 128) * DIMK + kc * 128;
        const uint8_t* gB = (const uint8_t*)g_Xq + (size_t)(nt * 256) * DIMK + kc * 128;
        #pragma unroll
        for (int i = 0; i < 4; i++) {
            const int idx = tid + i * 256;
            const int r = idx >> 3, ch = idx & 7;
            const uint32_t doff = (uint32_t)r * 128u + ((uint32_t)(ch ^ (r & 7)) << 4);
            cp16(dst + doff, gA + (size_t)r * DIMK + ch * 16);
        }
        #pragma unroll
        for (int i = 0; i < 8; i++) {
            const int idx = tid + i * 256;
            const int r = idx >> 3, ch = idx & 7;
            const uint32_t doff = (uint32_t)r * 128u + ((uint32_t)(ch ^ (r & 7)) << 4);
            cp16(dst + 16384u + doff, gB + (size_t)r * DIMK + ch * 16);
        }
    }
    asm volatile("cp.async.commit_group;" ::: "memory");
}

__global__ void __launch_bounds__(256) koleo_argmax_kernel() {
    extern __shared__ unsigned char smem[];
    const uint32_t sbase = smem_u32(smem);
    uint32_t* jtab = (uint32_t*)(smem + 4 * STAGE_BYTES);
    const int tid = threadIdx.x;
    const int lane = tid & 31;
    const int wid = tid >> 5;
    const int wm = wid & 1;        // rows [wm*64, wm*64+64)
    const int wn = wid >> 1;       // cols [wn*64, wn*64+64)
    const int cta = blockIdx.x;
    const int m = (NJOBS_T - cta + NCTA - 1) / NCTA;
    const int S = m * 8;

    if (tid < 8 && tid < m) jtab[tid] = job_decode(cta + tid * NCTA);
    __syncthreads();

    int c[4][8][4];   // s32 accumulators
    #pragma unroll
    for (int a = 0; a < 4; a++)
        #pragma unroll
        for (int b = 0; b < 8; b++)
            #pragma unroll
            for (int r = 0; r < 4; r++) c[a][b][r] = 0;

    copy_stream(sbase, jtab, 0, S, tid);
    copy_stream(sbase, jtab, 1, S, tid);
    copy_stream(sbase, jtab, 2, S, tid);

    for (int s = 0; s < S; s++) {
        asm volatile("cp.async.wait_group 2;" ::: "memory");
        __syncthreads();
        copy_stream(sbase, jtab, s + 3, S, tid);

        const uint32_t A = sbase + (uint32_t)(s & 3) * STAGE_BYTES;
        const uint32_t B = A + 16384u;

        #pragma unroll
        for (int t = 0; t < 4; t++) {     // k32 steps within the 128B chunk
            const uint32_t kc = (uint32_t)(t << 1) + (uint32_t)(lane >> 4);
            uint32_t bf[4][4], af[4][4];
            #pragma unroll
            for (int nb = 0; nb < 4; nb++) {
                const uint32_t r = (uint32_t)(wn * 64 + nb * 16 + (lane & 15));
                const uint32_t addr = B + r * 128u + ((kc ^ (r & 7u)) << 4);
                ldsm4(bf[nb][0], bf[nb][1], bf[nb][2], bf[nb][3], addr);
            }
            #pragma unroll
            for (int mt = 0; mt < 4; mt++) {
                const uint32_t r = (uint32_t)(wm * 64 + mt * 16 + (lane & 15));
                const uint32_t addr = A + r * 128u + ((kc ^ (r & 7u)) << 4);
                ldsm4(af[mt][0], af[mt][1], af[mt][2], af[mt][3], addr);
            }
            #pragma unroll
            for (int mt = 0; mt < 4; mt++)
                #pragma unroll
                for (int j = 0; j < 8; j++)
                    mma16832i(c[mt][j], af[mt][0], af[mt][1], af[mt][2], af[mt][3],
                              bf[j >> 1][j & 1], bf[j >> 1][2 + (j & 1)]);
        }

        if ((s & 7) == 7) {
            const uint32_t rbnt = jtab[s >> 3];
            const int rb = (int)(rbnt >> 8), nt = (int)(rbnt & 255u);
            const int colb = nt * 256 + wn * 64;
            const int rowb = rb * 128 + wm * 64;

            // ---- column-side fold (symmetry): per-column max over 128 rows ----
            #pragma unroll
            for (int j = 0; j < 8; j++) {
                #pragma unroll
                for (int h = 0; h < 2; h++) {
                    const int gcol = colb + j * 8 + (lane & 3) * 2 + h;
                    int cv = -2147483647; int cr = 0;
                    #pragma unroll
                    for (int mt = 0; mt < 4; mt++) {
                        #pragma unroll
                        for (int rh = 0; rh < 2; rh++) {
                            const int v = c[mt][j][rh * 2 + h];
                            const int grow = rowb + mt * 16 + (lane >> 2) + rh * 8;
                            if (grow != gcol && (v > cv || (v == cv && grow < cr))) {
                                cv = v; cr = grow;
                            }
                        }
                    }
                    unsigned long long key =
                        ((unsigned long long)ienc(cv) << 32) |
                        (unsigned long long)(0xFFFFFFFFu - (uint32_t)cr);
                    #pragma unroll
                    for (int o = 4; o <= 16; o <<= 1) {
                        const unsigned long long ok = __shfl_xor_sync(0xFFFFFFFFu, key, o);
                        if (ok > key) key = ok;
                    }
                    if (lane < 4) atomicMax(&g_best[gcol], key);
                }
            }

            // ---- row-side fold + accumulator reset ----
            int bestv[8];
            int besti[8];
            #pragma unroll
            for (int i = 0; i < 8; i++) { bestv[i] = -2147483647; besti[i] = 0; }
            #pragma unroll
            for (int mt = 0; mt < 4; mt++) {
                #pragma unroll
                for (int rh = 0; rh < 2; rh++) {
                    const int rloc = mt * 2 + rh;
                    const int grow = rowb + mt * 16 + (lane >> 2) + rh * 8;
                    #pragma unroll
                    for (int j = 0; j < 8; j++) {
                        const int v0 = c[mt][j][rh * 2];
                        const int v1 = c[mt][j][rh * 2 + 1];
                        const int col0 = colb + j * 8 + (lane & 3) * 2;
                        if (col0 != grow && v0 > bestv[rloc]) { bestv[rloc] = v0; besti[rloc] = col0; }
                        if (col0 + 1 != grow && v1 > bestv[rloc]) { bestv[rloc] = v1; besti[rloc] = col0 + 1; }
                        c[mt][j][rh * 2] = 0;
                        c[mt][j][rh * 2 + 1] = 0;
                    }
                }
            }
            #pragma unroll
            for (int rloc = 0; rloc < 8; rloc++) {
                unsigned long long key =
                    ((unsigned long long)ienc(bestv[rloc]) << 32) |
                    (unsigned long long)(0xFFFFFFFFu - (uint32_t)besti[rloc]);
                #pragma unroll
                for (int o = 1; o <= 2; o <<= 1) {
                    const unsigned long long ok = __shfl_xor_sync(0xFFFFFFFFu, key, o);
                    if (ok > key) key = ok;
                }
                if ((lane & 3) == 0) {
                    const int grow = rowb + (rloc >> 1) * 16 + (lane >> 2) + (rloc & 1) * 8;
                    atomicMax(&g_best[grow], key);
                }
            }
        }
    }
}

// ---------------- kernel 3: exact fp32 distance to argmax neighbor ----------------
__global__ void koleo_dist_kernel() {
    const int i = blockIdx.x;
    const int tid = threadIdx.x;  // 128
    const int j = (int)(0xFFFFFFFFu - (uint32_t)g_best[i]);
    const float4* a = (const float4*)(g_Xn + (size_t)i * DIMK);
    const float4* b = (const float4*)(g_Xn + (size_t)j * DIMK);
    float s = 0.f;
    #pragma unroll
    for (int t = 0; t < 2; t++) {
        const int idx = tid + t * 128;
        const float4 av = a[idx], bv = b[idx];
        const float d0 = av.x - bv.x + 1e-8f;
        const float d1 = av.y - bv.y + 1e-8f;
        const float d2 = av.z - bv.z + 1e-8f;
        const float d3 = av.w - bv.w + 1e-8f;
        s += d0 * d0 + d1 * d1 + d2 * d2 + d3 * d3;
    }
    #pragma unroll
    for (int o = 16; o; o >>= 1) s += __shfl_xor_sync(0xFFFFFFFFu, s, o);
    __shared__ float ws[4];
    if ((tid & 31) == 0) ws[tid >> 5] = s;
    __syncthreads();
    if (tid == 0) {
        const float t = ws[0] + ws[1] + ws[2] + ws[3];
        g_logd[i] = logf(sqrtf(t) + 1e-8f);
    }
}

// ---------------- kernel 4: deterministic mean reduction ----------------
__global__ void koleo_finish_kernel(float* __restrict__ out) {
    const int tid = threadIdx.x;  // 1024
    float s = 0.f;
    #pragma unroll
    for (int t = 0; t < 8; t++) s += g_logd[tid + t * 1024];
    #pragma unroll
    for (int o = 16; o; o >>= 1) s += __shfl_xor_sync(0xFFFFFFFFu, s, o);
    __shared__ float ws[32];
    if ((tid & 31) == 0) ws[tid >> 5] = s;
    __syncthreads();
    if (tid == 0) {
        float t = 0.f;
        #pragma unroll
        for (int i = 0; i < 32; i++) t += ws[i];
        out[0] = -(t / 8192.f);
    }
}

// ---------------- launch ----------------
extern "C" void kernel_launch(void* const* d_in, const int* in_sizes, int n_in,
                              void* d_out, int out_size) {
    (void)in_sizes; (void)n_in; (void)out_size;
    const float* x = (const float*)d_in[0];
    const int smem_bytes = 4 * 49152 + 64;
    cudaFuncSetAttribute(koleo_argmax_kernel, cudaFuncAttributeMaxDynamicSharedMemorySize,
                         smem_bytes);
    koleo_normalize_kernel<<<N_ROWS, 256>>>(x);
    koleo_argmax_kernel<<<NCTA, 256, smem_bytes>>>();
    koleo_dist_kernel<<<N_ROWS, 128>>>();
    koleo_finish_kernel<<<1, 1024>>>((float*)d_out);
}

// round 8
// speedup vs baseline: 1.4670x; 1.4670x over previous
#include <cuda_runtime.h>
#include <cuda_fp16.h>
#include <cstdint>
#include <math.h>

#define N_ROWS 8192
#define DIMK   1024
#define NCTA   148
#define NJOBS_T 1056         // upper-triangle 128x256 tiles
#define STAGE_BYTES 49152u

// ---------------- scratch (static device memory, no allocs) ----------------
__device__ __align__(16) float  g_Xn[N_ROWS * DIMK];   // 32 MB normalized fp32
__device__ __align__(16) __half g_Xh[N_ROWS * DIMK];   // 16 MB fp16 row-major
__device__ unsigned long long g_best[N_ROWS];          // packed (enc(val)<<32 | ~col)
__device__ float g_logd[N_ROWS];

// ---------------- helpers ----------------
__device__ __forceinline__ uint32_t smem_u32(const void* p) {
    uint32_t a;
    asm("{ .reg .u64 t; cvta.to.shared.u64 t, %1; cvt.u32.u64 %0, t; }" : "=r"(a) : "l"(p));
    return a;
}
__device__ __forceinline__ void cp16(uint32_t dst, const void* src) {
    asm volatile("cp.async.cg.shared.global [%0], [%1], 16;" :: "r"(dst), "l"(src));
}
__device__ __forceinline__ void ldsm4(uint32_t& r0, uint32_t& r1, uint32_t& r2, uint32_t& r3,
                                      uint32_t addr) {
    asm volatile("ldmatrix.sync.aligned.m8n8.x4.shared.b16 {%0,%1,%2,%3}, [%4];"
                 : "=r"(r0), "=r"(r1), "=r"(r2), "=r"(r3) : "r"(addr));
}
__device__ __forceinline__ void mma16816h(uint32_t* c, uint32_t a0, uint32_t a1, uint32_t a2,
                                          uint32_t a3, uint32_t b0, uint32_t b1) {
    asm volatile("mma.sync.aligned.m16n8k16.row.col.f16.f16.f16.f16 "
                 "{%0,%1}, {%2,%3,%4,%5}, {%6,%7}, {%0,%1};"
                 : "+r"(c[0]), "+r"(c[1])
                 : "r"(a0), "r"(a1), "r"(a2), "r"(a3), "r"(b0), "r"(b1));
}
// monotonic float->u32 (total order preserved, incl. negatives)
__device__ __forceinline__ uint32_t fenc(float v) {
    const uint32_t u = __float_as_uint(v);
    return (u & 0x80000000u) ? ~u : (u | 0x80000000u);
}
// job index -> (rb, nt); pair u (rb = 2u,2u+1) has 2*(32-u) jobs; S(u) = u*(65-u).
__device__ __forceinline__ uint32_t job_decode(int jj) {
    int u = 0;
    #pragma unroll 1
    while ((u + 1) * (65 - (u + 1)) <= jj) u++;
    const int r = jj - u * (65 - u);
    const int cnt = 32 - u;
    const int rb = 2 * u + (r >= cnt);
    const int nt = u + (r >= cnt ? r - cnt : r);
    return ((uint32_t)rb << 8) | (uint32_t)nt;
}

// ---------------- kernel 1: normalize rows, write fp32 + fp16; reset g_best ----------------
__global__ void koleo_normalize_kernel(const float* __restrict__ x) {
    const int row = blockIdx.x;
    const int tid = threadIdx.x;  // 256 threads, 4 elems each
    if (tid == 0) g_best[row] = 0ull;
    const float4 v = ((const float4*)(x + (size_t)row * DIMK))[tid];
    float ss = v.x * v.x + v.y * v.y + v.z * v.z + v.w * v.w;
    #pragma unroll
    for (int o = 16; o; o >>= 1) ss += __shfl_xor_sync(0xFFFFFFFFu, ss, o);
    __shared__ float ws[9];
    if ((tid & 31) == 0) ws[tid >> 5] = ss;
    __syncthreads();
    if (tid == 0) {
        float t = 0.f;
        #pragma unroll
        for (int i = 0; i < 8; i++) t += ws[i];
        ws[8] = 1.f / fmaxf(sqrtf(t), 1e-8f);
    }
    __syncthreads();
    const float s = ws[8];
    float4 y; y.x = v.x * s; y.y = v.y * s; y.z = v.z * s; y.w = v.w * s;
    ((float4*)(g_Xn + (size_t)row * DIMK))[tid] = y;

    __half2 h0 = __floats2half2_rn(y.x, y.y);
    __half2 h1 = __floats2half2_rn(y.z, y.w);
    uint2 u;
    u.x = *(const uint32_t*)&h0;
    u.y = *(const uint32_t*)&h1;
    *(uint2*)(g_Xh + (size_t)row * DIMK + tid * 4) = u;
}

// ---------------- kernel 2: persistent fp16 GEMM over the upper triangle ----------------
// 148 CTAs; CTA c runs triangle-jobs c, c+148, ... Tile = 128 rows x 256 cols.
// Stage = K-chunk 64 (16/job), streamed continuously: 4 smem buffers, depth 3,
// one __syncthreads per stage. ldmatrix fragments double-buffered across k16-steps.
// Each finished tile folds BOTH row-side and column-side candidates into g_best.

__device__ __forceinline__ void copy_stream(uint32_t sbase, const uint32_t* jtab,
                                            int s, int S, int tid) {
    if (s < S) {
        const uint32_t rbnt = jtab[s >> 4];
        const int rb = (int)(rbnt >> 8), nt = (int)(rbnt & 255u), kc = s & 15;
        const uint32_t dst = sbase + (uint32_t)(s & 3) * STAGE_BYTES;
        const __half* gA = g_Xh + (size_t)(rb * 128) * DIMK + kc * 64;
        const __half* gB = g_Xh + (size_t)(nt * 256) * DIMK + kc * 64;
        #pragma unroll
        for (int i = 0; i < 4; i++) {
            const int idx = tid + i * 256;
            const int r = idx >> 3, ch = idx & 7;
            const uint32_t doff = (uint32_t)r * 128u + ((uint32_t)(ch ^ (r & 7)) << 4);
            cp16(dst + doff, gA + (size_t)r * DIMK + ch * 8);
        }
        #pragma unroll
        for (int i = 0; i < 8; i++) {
            const int idx = tid + i * 256;
            const int r = idx >> 3, ch = idx & 7;
            const uint32_t doff = (uint32_t)r * 128u + ((uint32_t)(ch ^ (r & 7)) << 4);
            cp16(dst + 16384u + doff, gB + (size_t)r * DIMK + ch * 8);
        }
    }
    asm volatile("cp.async.commit_group;" ::: "memory");
}

__global__ void __launch_bounds__(256) koleo_argmax_kernel() {
    extern __shared__ unsigned char smem[];
    const uint32_t sbase = smem_u32(smem);
    uint32_t* jtab = (uint32_t*)(smem + 4 * STAGE_BYTES);
    const int tid = threadIdx.x;
    const int lane = tid & 31;
    const int wid = tid >> 5;
    const int wm = wid & 1;        // rows [wm*64, wm*64+64)
    const int wn = wid >> 1;       // cols [wn*64, wn*64+64)
    const int cta = blockIdx.x;
    const int m = (NJOBS_T - cta + NCTA - 1) / NCTA;
    const int S = m * 16;

    if (tid < 8 && tid < m) jtab[tid] = job_decode(cta + tid * NCTA);
    __syncthreads();

    // per-warp fragment base rows (constant across loop)
    const uint32_t rB0 = (uint32_t)(wn * 64 + (lane & 15));
    const uint32_t rA0 = (uint32_t)(wm * 64 + (lane & 15));

    uint32_t c2[4][8][2];   // fp16x2 accumulators
    #pragma unroll
    for (int a = 0; a < 4; a++)
        #pragma unroll
        for (int b = 0; b < 8; b++) { c2[a][b][0] = 0u; c2[a][b][1] = 0u; }

    copy_stream(sbase, jtab, 0, S, tid);
    copy_stream(sbase, jtab, 1, S, tid);
    copy_stream(sbase, jtab, 2, S, tid);

    for (int s = 0; s < S; s++) {
        asm volatile("cp.async.wait_group 2;" ::: "memory");
        __syncthreads();
        copy_stream(sbase, jtab, s + 3, S, tid);

        const uint32_t A = sbase + (uint32_t)(s & 3) * STAGE_BYTES;
        const uint32_t B = A + 16384u;

        uint32_t bf[2][4][4], af[2][4][4];   // double-buffered fragments
        // preload k16-step 0 into slot 0
        {
            const uint32_t kc = (uint32_t)(lane >> 4);
            #pragma unroll
            for (int nb = 0; nb < 4; nb++) {
                const uint32_t r = rB0 + nb * 16;
                ldsm4(bf[0][nb][0], bf[0][nb][1], bf[0][nb][2], bf[0][nb][3],
                      B + r * 128u + ((kc ^ (r & 7u)) << 4));
            }
            #pragma unroll
            for (int mt = 0; mt < 4; mt++) {
                const uint32_t r = rA0 + mt * 16;
                ldsm4(af[0][mt][0], af[0][mt][1], af[0][mt][2], af[0][mt][3],
                      A + r * 128u + ((kc ^ (r & 7u)) << 4));
            }
        }
        #pragma unroll
        for (int t = 0; t < 4; t++) {
            const int cur = t & 1, nxt = cur ^ 1;
            if (t < 3) {   // prefetch next k16-step's fragments while cur MMAs issue
                const uint32_t kc = (uint32_t)((t + 1) << 1) + (uint32_t)(lane >> 4);
                #pragma unroll
                for (int nb = 0; nb < 4; nb++) {
                    const uint32_t r = rB0 + nb * 16;
                    ldsm4(bf[nxt][nb][0], bf[nxt][nb][1], bf[nxt][nb][2], bf[nxt][nb][3],
                          B + r * 128u + ((kc ^ (r & 7u)) << 4));
                }
                #pragma unroll
                for (int mt = 0; mt < 4; mt++) {
                    const uint32_t r = rA0 + mt * 16;
                    ldsm4(af[nxt][mt][0], af[nxt][mt][1], af[nxt][mt][2], af[nxt][mt][3],
                          A + r * 128u + ((kc ^ (r & 7u)) << 4));
                }
            }
            #pragma unroll
            for (int mt = 0; mt < 4; mt++)
                #pragma unroll
                for (int j = 0; j < 8; j++)
                    mma16816h(c2[mt][j], af[cur][mt][0], af[cur][mt][1],
                              af[cur][mt][2], af[cur][mt][3],
                              bf[cur][j >> 1][j & 1], bf[cur][j >> 1][2 + (j & 1)]);
        }

        if ((s & 15) == 15) {
            const uint32_t rbnt = jtab[s >> 4];
            const int rb = (int)(rbnt >> 8), nt = (int)(rbnt & 255u);
            const int colb = nt * 256 + wn * 64;
            const int rowb = rb * 128 + wm * 64;

            // ---- column-side fold (symmetry): per-column max over 128 rows ----
            #pragma unroll
            for (int j = 0; j < 8; j++) {
                #pragma unroll
                for (int h = 0; h < 2; h++) {
                    const int gcol = colb + j * 8 + (lane & 3) * 2 + h;
                    float cv = -2.f; int cr = 0;
                    #pragma unroll
                    for (int mt = 0; mt < 4; mt++) {
                        #pragma unroll
                        for (int rh = 0; rh < 2; rh++) {
                            const __half2 hv = *(const __half2*)&c2[mt][j][rh];
                            const float v = h ? __high2float(hv) : __low2float(hv);
                            const int grow = rowb + mt * 16 + (lane >> 2) + rh * 8;
                            if (grow != gcol && (v > cv || (v == cv && grow < cr))) {
                                cv = v; cr = grow;
                            }
                        }
                    }
                    unsigned long long key =
                        ((unsigned long long)fenc(cv) << 32) |
                        (unsigned long long)(0xFFFFFFFFu - (uint32_t)cr);
                    #pragma unroll
                    for (int o = 4; o <= 16; o <<= 1) {
                        const unsigned long long ok = __shfl_xor_sync(0xFFFFFFFFu, key, o);
                        if (ok > key) key = ok;
                    }
                    if (lane < 4) atomicMax(&g_best[gcol], key);
                }
            }

            // ---- row-side fold + accumulator reset ----
            float bestv[8];
            int   besti[8];
            #pragma unroll
            for (int i = 0; i < 8; i++) { bestv[i] = -2.f; besti[i] = 0; }
            #pragma unroll
            for (int mt = 0; mt < 4; mt++) {
                #pragma unroll
                for (int rh = 0; rh < 2; rh++) {
                    const int rloc = mt * 2 + rh;
                    const int grow = rowb + mt * 16 + (lane >> 2) + rh * 8;
                    #pragma unroll
                    for (int j = 0; j < 8; j++) {
                        const __half2 hv = *(const __half2*)&c2[mt][j][rh];
                        const float v0 = __low2float(hv);
                        const float v1 = __high2float(hv);
                        const int col0 = colb + j * 8 + (lane & 3) * 2;
                        if (col0 != grow && v0 > bestv[rloc]) { bestv[rloc] = v0; besti[rloc] = col0; }
                        if (col0 + 1 != grow && v1 > bestv[rloc]) { bestv[rloc] = v1; besti[rloc] = col0 + 1; }
                        c2[mt][j][rh] = 0u;
                    }
                }
            }
            #pragma unroll
            for (int rloc = 0; rloc < 8; rloc++) {
                unsigned long long key =
                    ((unsigned long long)fenc(bestv[rloc]) << 32) |
                    (unsigned long long)(0xFFFFFFFFu - (uint32_t)besti[rloc]);
                #pragma unroll
                for (int o = 1; o <= 2; o <<= 1) {
                    const unsigned long long ok = __shfl_xor_sync(0xFFFFFFFFu, key, o);
                    if (ok > key) key = ok;
                }
                if ((lane & 3) == 0) {
                    const int grow = rowb + (rloc >> 1) * 16 + (lane >> 2) + (rloc & 1) * 8;
                    atomicMax(&g_best[grow], key);
                }
            }
        }
    }
}

// ---------------- kernel 3: exact fp32 distance to argmax neighbor ----------------
__global__ void koleo_dist_kernel() {
    const int i = blockIdx.x;
    const int tid = threadIdx.x;  // 128
    const int j = (int)(0xFFFFFFFFu - (uint32_t)g_best[i]);
    const float4* a = (const float4*)(g_Xn + (size_t)i * DIMK);
    const float4* b = (const float4*)(g_Xn + (size_t)j * DIMK);
    float s = 0.f;
    #pragma unroll
    for (int t = 0; t < 2; t++) {
        const int idx = tid + t * 128;
        const float4 av = a[idx], bv = b[idx];
        const float d0 = av.x - bv.x + 1e-8f;
        const float d1 = av.y - bv.y + 1e-8f;
        const float d2 = av.z - bv.z + 1e-8f;
        const float d3 = av.w - bv.w + 1e-8f;
        s += d0 * d0 + d1 * d1 + d2 * d2 + d3 * d3;
    }
    #pragma unroll
    for (int o = 16; o; o >>= 1) s += __shfl_xor_sync(0xFFFFFFFFu, s, o);
    __shared__ float ws[4];
    if ((tid & 31) == 0) ws[tid >> 5] = s;
    __syncthreads();
    if (tid == 0) {
        const float t = ws[0] + ws[1] + ws[2] + ws[3];
        g_logd[i] = logf(sqrtf(t) + 1e-8f);
    }
}

// ---------------- kernel 4: deterministic mean reduction ----------------
__global__ void koleo_finish_kernel(float* __restrict__ out) {
    const int tid = threadIdx.x;  // 1024
    float s = 0.f;
    #pragma unroll
    for (int t = 0; t < 8; t++) s += g_logd[tid + t * 1024];
    #pragma unroll
    for (int o = 16; o; o >>= 1) s += __shfl_xor_sync(0xFFFFFFFFu, s, o);
    __shared__ float ws[32];
    if ((tid & 31) == 0) ws[tid >> 5] = s;
    __syncthreads();
    if (tid == 0) {
        float t = 0.f;
        #pragma unroll
        for (int i = 0; i < 32; i++) t += ws[i];
        out[0] = -(t / 8192.f);
    }
}

// ---------------- launch ----------------
extern "C" void kernel_launch(void* const* d_in, const int* in_sizes, int n_in,
                              void* d_out, int out_size) {
    (void)in_sizes; (void)n_in; (void)out_size;
    const float* x = (const float*)d_in[0];
    const int smem_bytes = 4 * 49152 + 64;
    cudaFuncSetAttribute(koleo_argmax_kernel, cudaFuncAttributeMaxDynamicSharedMemorySize,
                         smem_bytes);
    koleo_normalize_kernel<<<N_ROWS, 256>>>(x);
    koleo_argmax_kernel<<<NCTA, 256, smem_bytes>>>();
    koleo_dist_kernel<<<N_ROWS, 128>>>();
    koleo_finish_kernel<<<1, 1024>>>((float*)d_out);
}

// round 9
// speedup vs baseline: 2.5592x; 1.7445x over previous
#include <cuda_runtime.h>
#include <cuda_fp16.h>
#include <cstdint>
#include <math.h>

#define N_ROWS 8192
#define DIMK   1024
#define NCTA2  296           // 2 CTAs per SM
#define NJOBS_T 1056         // upper-triangle 128x256 tiles
#define STAGE_BYTES 49152u

// ---------------- scratch (static device memory, no allocs) ----------------
__device__ __align__(16) float  g_Xn[N_ROWS * DIMK];   // 32 MB normalized fp32
__device__ __align__(16) __half g_Xh[N_ROWS * DIMK];   // 16 MB fp16 row-major
__device__ unsigned long long g_best[N_ROWS];          // packed (enc(val)<<32 | ~col)
__device__ float g_logd[N_ROWS];

// ---------------- helpers ----------------
__device__ __forceinline__ uint32_t smem_u32(const void* p) {
    uint32_t a;
    asm("{ .reg .u64 t; cvta.to.shared.u64 t, %1; cvt.u32.u64 %0, t; }" : "=r"(a) : "l"(p));
    return a;
}
__device__ __forceinline__ void cp16(uint32_t dst, const void* src) {
    asm volatile("cp.async.cg.shared.global [%0], [%1], 16;" :: "r"(dst), "l"(src));
}
__device__ __forceinline__ void ldsm4(uint32_t& r0, uint32_t& r1, uint32_t& r2, uint32_t& r3,
                                      uint32_t addr) {
    asm volatile("ldmatrix.sync.aligned.m8n8.x4.shared.b16 {%0,%1,%2,%3}, [%4];"
                 : "=r"(r0), "=r"(r1), "=r"(r2), "=r"(r3) : "r"(addr));
}
__device__ __forceinline__ void mma16816h(uint32_t* c, uint32_t a0, uint32_t a1, uint32_t a2,
                                          uint32_t a3, uint32_t b0, uint32_t b1) {
    asm volatile("mma.sync.aligned.m16n8k16.row.col.f16.f16.f16.f16 "
                 "{%0,%1}, {%2,%3,%4,%5}, {%6,%7}, {%0,%1};"
                 : "+r"(c[0]), "+r"(c[1])
                 : "r"(a0), "r"(a1), "r"(a2), "r"(a3), "r"(b0), "r"(b1));
}
// monotonic float->u32 (total order preserved, incl. negatives)
__device__ __forceinline__ uint32_t fenc(float v) {
    const uint32_t u = __float_as_uint(v);
    return (u & 0x80000000u) ? ~u : (u | 0x80000000u);
}
// job index -> (rb, nt); pair u (rb = 2u,2u+1) has 2*(32-u) jobs; S(u) = u*(65-u).
__device__ __forceinline__ uint32_t job_decode(int jj) {
    int u = 0;
    #pragma unroll 1
    while ((u + 1) * (65 - (u + 1)) <= jj) u++;
    const int r = jj - u * (65 - u);
    const int cnt = 32 - u;
    const int rb = 2 * u + (r >= cnt);
    const int nt = u + (r >= cnt ? r - cnt : r);
    return ((uint32_t)rb << 8) | (uint32_t)nt;
}

// ---------------- kernel 1: normalize rows, write fp32 + fp16; reset g_best ----------------
__global__ void koleo_normalize_kernel(const float* __restrict__ x) {
    const int row = blockIdx.x;
    const int tid = threadIdx.x;  // 256 threads, 4 elems each
    if (tid == 0) g_best[row] = 0ull;
    const float4 v = ((const float4*)(x + (size_t)row * DIMK))[tid];
    float ss = v.x * v.x + v.y * v.y + v.z * v.z + v.w * v.w;
    #pragma unroll
    for (int o = 16; o; o >>= 1) ss += __shfl_xor_sync(0xFFFFFFFFu, ss, o);
    __shared__ float ws[9];
    if ((tid & 31) == 0) ws[tid >> 5] = ss;
    __syncthreads();
    if (tid == 0) {
        float t = 0.f;
        #pragma unroll
        for (int i = 0; i < 8; i++) t += ws[i];
        ws[8] = 1.f / fmaxf(sqrtf(t), 1e-8f);
    }
    __syncthreads();
    const float s = ws[8];
    float4 y; y.x = v.x * s; y.y = v.y * s; y.z = v.z * s; y.w = v.w * s;
    ((float4*)(g_Xn + (size_t)row * DIMK))[tid] = y;

    __half2 h0 = __floats2half2_rn(y.x, y.y);
    __half2 h1 = __floats2half2_rn(y.z, y.w);
    uint2 u;
    u.x = *(const uint32_t*)&h0;
    u.y = *(const uint32_t*)&h1;
    *(uint2*)(g_Xh + (size_t)row * DIMK + tid * 4) = u;
}

// ---------------- kernel 2: persistent fp16 GEMM over the upper triangle ----------------
// 296 CTAs (2/SM); CTA c runs triangle-jobs c, c+296, ... Tile = 128 rows x 256 cols.
// Stage = K-chunk 64 (16/job): A 128x64 (16KB) + B 256x64 (32KB) = 48KB/buffer,
// 2 buffers, prefetch depth 1, one __syncthreads per stage.
// Each finished tile folds BOTH row-side and column-side candidates into g_best.

__device__ __forceinline__ void copy_stream(uint32_t sbase, const uint32_t* jtab,
                                            int s, int S, int tid) {
    if (s < S) {
        const uint32_t rbnt = jtab[s >> 4];
        const int rb = (int)(rbnt >> 8), nt = (int)(rbnt & 255u), kc = s & 15;
        const uint32_t dst = sbase + (uint32_t)(s & 1) * STAGE_BYTES;
        const __half* gA = g_Xh + (size_t)(rb * 128) * DIMK + kc * 64;
        const __half* gB = g_Xh + (size_t)(nt * 256) * DIMK + kc * 64;
        #pragma unroll
        for (int i = 0; i < 4; i++) {
            const int idx = tid + i * 256;
            const int r = idx >> 3, ch = idx & 7;
            const uint32_t doff = (uint32_t)r * 128u + ((uint32_t)(ch ^ (r & 7)) << 4);
            cp16(dst + doff, gA + (size_t)r * DIMK + ch * 8);
        }
        #pragma unroll
        for (int i = 0; i < 8; i++) {
            const int idx = tid + i * 256;
            const int r = idx >> 3, ch = idx & 7;
            const uint32_t doff = (uint32_t)r * 128u + ((uint32_t)(ch ^ (r & 7)) << 4);
            cp16(dst + 16384u + doff, gB + (size_t)r * DIMK + ch * 8);
        }
    }
    asm volatile("cp.async.commit_group;" ::: "memory");
}

__global__ void __launch_bounds__(256, 2) koleo_argmax_kernel() {
    extern __shared__ unsigned char smem[];
    const uint32_t sbase = smem_u32(smem);
    uint32_t* jtab = (uint32_t*)(smem + 2 * STAGE_BYTES);
    const int tid = threadIdx.x;
    const int lane = tid & 31;
    const int wid = tid >> 5;
    const int wm = wid & 1;        // rows [wm*64, wm*64+64)
    const int wn = wid >> 1;       // cols [wn*64, wn*64+64)
    const int cta = blockIdx.x;
    const int m = (NJOBS_T - cta + NCTA2 - 1) / NCTA2;   // jobs for this CTA (<=4)
    const int S = m * 16;

    if (tid < 4 && tid < m) jtab[tid] = job_decode(cta + tid * NCTA2);
    __syncthreads();

    uint32_t c2[4][8][2];   // fp16x2 accumulators
    #pragma unroll
    for (int a = 0; a < 4; a++)
        #pragma unroll
        for (int b = 0; b < 8; b++) { c2[a][b][0] = 0u; c2[a][b][1] = 0u; }

    copy_stream(sbase, jtab, 0, S, tid);

    for (int s = 0; s < S; s++) {
        asm volatile("cp.async.wait_group 0;" ::: "memory");
        __syncthreads();                 // copy(s) visible; stage s-1 reads of buf (s+1)&1 done
        copy_stream(sbase, jtab, s + 1, S, tid);   // overlaps compute(s)

        const uint32_t A = sbase + (uint32_t)(s & 1) * STAGE_BYTES;
        const uint32_t B = A + 16384u;

        #pragma unroll
        for (int t = 0; t < 4; t++) {
            const uint32_t kc = (uint32_t)(t << 1) + (uint32_t)(lane >> 4);
            uint32_t bf[4][4], af[4][4];
            #pragma unroll
            for (int nb = 0; nb < 4; nb++) {
                const uint32_t r = (uint32_t)(wn * 64 + nb * 16 + (lane & 15));
                const uint32_t addr = B + r * 128u + ((kc ^ (r & 7u)) << 4);
                ldsm4(bf[nb][0], bf[nb][1], bf[nb][2], bf[nb][3], addr);
            }
            #pragma unroll
            for (int mt = 0; mt < 4; mt++) {
                const uint32_t r = (uint32_t)(wm * 64 + mt * 16 + (lane & 15));
                const uint32_t addr = A + r * 128u + ((kc ^ (r & 7u)) << 4);
                ldsm4(af[mt][0], af[mt][1], af[mt][2], af[mt][3], addr);
            }
            #pragma unroll
            for (int mt = 0; mt < 4; mt++)
                #pragma unroll
                for (int j = 0; j < 8; j++)
                    mma16816h(c2[mt][j], af[mt][0], af[mt][1], af[mt][2], af[mt][3],
                              bf[j >> 1][j & 1], bf[j >> 1][2 + (j & 1)]);
        }

        if ((s & 15) == 15) {
            const uint32_t rbnt = jtab[s >> 4];
            const int rb = (int)(rbnt >> 8), nt = (int)(rbnt & 255u);
            const int colb = nt * 256 + wn * 64;
            const int rowb = rb * 128 + wm * 64;

            // ---- column-side fold (symmetry): per-column max over 128 rows ----
            #pragma unroll
            for (int j = 0; j < 8; j++) {
                #pragma unroll
                for (int h = 0; h < 2; h++) {
                    const int gcol = colb + j * 8 + (lane & 3) * 2 + h;
                    float cv = -2.f; int cr = 0;
                    #pragma unroll
                    for (int mt = 0; mt < 4; mt++) {
                        #pragma unroll
                        for (int rh = 0; rh < 2; rh++) {
                            const __half2 hv = *(const __half2*)&c2[mt][j][rh];
                            const float v = h ? __high2float(hv) : __low2float(hv);
                            const int grow = rowb + mt * 16 + (lane >> 2) + rh * 8;
                            if (grow != gcol && (v > cv || (v == cv && grow < cr))) {
                                cv = v; cr = grow;
                            }
                        }
                    }
                    unsigned long long key =
                        ((unsigned long long)fenc(cv) << 32) |
                        (unsigned long long)(0xFFFFFFFFu - (uint32_t)cr);
                    #pragma unroll
                    for (int o = 4; o <= 16; o <<= 1) {
                        const unsigned long long ok = __shfl_xor_sync(0xFFFFFFFFu, key, o);
                        if (ok > key) key = ok;
                    }
                    if (lane < 4) atomicMax(&g_best[gcol], key);
                }
            }

            // ---- row-side fold + accumulator reset ----
            float bestv[8];
            int   besti[8];
            #pragma unroll
            for (int i = 0; i < 8; i++) { bestv[i] = -2.f; besti[i] = 0; }
            #pragma unroll
            for (int mt = 0; mt < 4; mt++) {
                #pragma unroll
                for (int rh = 0; rh < 2; rh++) {
                    const int rloc = mt * 2 + rh;
                    const int grow = rowb + mt * 16 + (lane >> 2) + rh * 8;
                    #pragma unroll
                    for (int j = 0; j < 8; j++) {
                        const __half2 hv = *(const __half2*)&c2[mt][j][rh];
                        const float v0 = __low2float(hv);
                        const float v1 = __high2float(hv);
                        const int col0 = colb + j * 8 + (lane & 3) * 2;
                        if (col0 != grow && v0 > bestv[rloc]) { bestv[rloc] = v0; besti[rloc] = col0; }
                        if (col0 + 1 != grow && v1 > bestv[rloc]) { bestv[rloc] = v1; besti[rloc] = col0 + 1; }
                        c2[mt][j][rh] = 0u;
                    }
                }
            }
            #pragma unroll
            for (int rloc = 0; rloc < 8; rloc++) {
                unsigned long long key =
                    ((unsigned long long)fenc(bestv[rloc]) << 32) |
                    (unsigned long long)(0xFFFFFFFFu - (uint32_t)besti[rloc]);
                #pragma unroll
                for (int o = 1; o <= 2; o <<= 1) {
                    const unsigned long long ok = __shfl_xor_sync(0xFFFFFFFFu, key, o);
                    if (ok > key) key = ok;
                }
                if ((lane & 3) == 0) {
                    const int grow = rowb + (rloc >> 1) * 16 + (lane >> 2) + (rloc & 1) * 8;
                    atomicMax(&g_best[grow], key);
                }
            }
        }
    }
}

// ---------------- kernel 3: exact fp32 distance to argmax neighbor ----------------
__global__ void koleo_dist_kernel() {
    const int i = blockIdx.x;
    const int tid = threadIdx.x;  // 128
    const int j = (int)(0xFFFFFFFFu - (uint32_t)g_best[i]);
    const float4* a = (const float4*)(g_Xn + (size_t)i * DIMK);
    const float4* b = (const float4*)(g_Xn + (size_t)j * DIMK);
    float s = 0.f;
    #pragma unroll
    for (int t = 0; t < 2; t++) {
        const int idx = tid + t * 128;
        const float4 av = a[idx], bv = b[idx];
        const float d0 = av.x - bv.x + 1e-8f;
        const float d1 = av.y - bv.y + 1e-8f;
        const float d2 = av.z - bv.z + 1e-8f;
        const float d3 = av.w - bv.w + 1e-8f;
        s += d0 * d0 + d1 * d1 + d2 * d2 + d3 * d3;
    }
    #pragma unroll
    for (int o = 16; o; o >>= 1) s += __shfl_xor_sync(0xFFFFFFFFu, s, o);
    __shared__ float ws[4];
    if ((tid & 31) == 0) ws[tid >> 5] = s;
    __syncthreads();
    if (tid == 0) {
        const float t = ws[0] + ws[1] + ws[2] + ws[3];
        g_logd[i] = logf(sqrtf(t) + 1e-8f);
    }
}

// ---------------- kernel 4: deterministic mean reduction ----------------
__global__ void koleo_finish_kernel(float* __restrict__ out) {
    const int tid = threadIdx.x;  // 1024
    float s = 0.f;
    #pragma unroll
    for (int t = 0; t < 8; t++) s += g_logd[tid + t * 1024];
    #pragma unroll
    for (int o = 16; o; o >>= 1) s += __shfl_xor_sync(0xFFFFFFFFu, s, o);
    __shared__ float ws[32];
    if ((tid & 31) == 0) ws[tid >> 5] = s;
    __syncthreads();
    if (tid == 0) {
        float t = 0.f;
        #pragma unroll
        for (int i = 0; i < 32; i++) t += ws[i];
        out[0] = -(t / 8192.f);
    }
}

// ---------------- launch ----------------
extern "C" void kernel_launch(void* const* d_in, const int* in_sizes, int n_in,
                              void* d_out, int out_size) {
    (void)in_sizes; (void)n_in; (void)out_size;
    const float* x = (const float*)d_in[0];
    const int smem_bytes = 2 * 49152 + 64;
    cudaFuncSetAttribute(koleo_argmax_kernel, cudaFuncAttributeMaxDynamicSharedMemorySize,
                         smem_bytes);
    koleo_normalize_kernel<<<N_ROWS, 256>>>(x);
    koleo_argmax_kernel<<<NCTA2, 256, smem_bytes>>>();
    koleo_dist_kernel<<<N_ROWS, 128>>>();
    koleo_finish_kernel<<<1, 1024>>>((float*)d_out);
}

// round 10
// speedup vs baseline: 2.6249x; 1.0257x over previous
#include <cuda_runtime.h>
#include <cuda_fp16.h>
#include <cstdint>
#include <math.h>

#define N_ROWS 8192
#define DIMK   1024
#define NCTA3  444            // 3 CTAs per SM
#define NJOBS_T 2080          // triangle 128x128 tiles incl. diagonal: 64*65/2
#define STAGE_BYTES 32768u

// ---------------- scratch (static device memory, no allocs) ----------------
__device__ __align__(16) float  g_Xn[N_ROWS * DIMK];   // 32 MB normalized fp32
__device__ __align__(16) __half g_Xh[N_ROWS * DIMK];   // 16 MB fp16 row-major
__device__ unsigned long long g_best[N_ROWS];          // packed (enc(val)<<32 | ~col)
__device__ float g_logd[N_ROWS];

// ---------------- helpers ----------------
__device__ __forceinline__ uint32_t smem_u32(const void* p) {
    uint32_t a;
    asm("{ .reg .u64 t; cvta.to.shared.u64 t, %1; cvt.u32.u64 %0, t; }" : "=r"(a) : "l"(p));
    return a;
}
__device__ __forceinline__ void cp16(uint32_t dst, const void* src) {
    asm volatile("cp.async.cg.shared.global [%0], [%1], 16;" :: "r"(dst), "l"(src));
}
__device__ __forceinline__ void ldsm4(uint32_t& r0, uint32_t& r1, uint32_t& r2, uint32_t& r3,
                                      uint32_t addr) {
    asm volatile("ldmatrix.sync.aligned.m8n8.x4.shared.b16 {%0,%1,%2,%3}, [%4];"
                 : "=r"(r0), "=r"(r1), "=r"(r2), "=r"(r3) : "r"(addr));
}
__device__ __forceinline__ void mma16816h(uint32_t* c, uint32_t a0, uint32_t a1, uint32_t a2,
                                          uint32_t a3, uint32_t b0, uint32_t b1) {
    asm volatile("mma.sync.aligned.m16n8k16.row.col.f16.f16.f16.f16 "
                 "{%0,%1}, {%2,%3,%4,%5}, {%6,%7}, {%0,%1};"
                 : "+r"(c[0]), "+r"(c[1])
                 : "r"(a0), "r"(a1), "r"(a2), "r"(a3), "r"(b0), "r"(b1));
}
// monotonic float->u32 (total order preserved, incl. negatives)
__device__ __forceinline__ uint32_t fenc(float v) {
    const uint32_t u = __float_as_uint(v);
    return (u & 0x80000000u) ? ~u : (u | 0x80000000u);
}
// job index -> (rb, cb) over the 64x64 block triangle (cb >= rb).
// Row rb has (64 - rb) jobs; cumulative S(r) = r*(129-r)/2.
__device__ __forceinline__ uint32_t job_decode(int jj) {
    int u = 0;
    #pragma unroll 1
    while ((u + 1) * (129 - (u + 1)) / 2 <= jj) u++;
    const int c = u + (jj - u * (129 - u) / 2);
    return ((uint32_t)u << 8) | (uint32_t)c;
}

// ---------------- kernel 1: normalize rows, write fp32 + fp16; reset g_best ----------------
__global__ void koleo_normalize_kernel(const float* __restrict__ x) {
    const int row = blockIdx.x;
    const int tid = threadIdx.x;  // 256 threads, 4 elems each
    if (tid == 0) g_best[row] = 0ull;
    const float4 v = ((const float4*)(x + (size_t)row * DIMK))[tid];
    float ss = v.x * v.x + v.y * v.y + v.z * v.z + v.w * v.w;
    #pragma unroll
    for (int o = 16; o; o >>= 1) ss += __shfl_xor_sync(0xFFFFFFFFu, ss, o);
    __shared__ float ws[9];
    if ((tid & 31) == 0) ws[tid >> 5] = ss;
    __syncthreads();
    if (tid == 0) {
        float t = 0.f;
        #pragma unroll
        for (int i = 0; i < 8; i++) t += ws[i];
        ws[8] = 1.f / fmaxf(sqrtf(t), 1e-8f);
    }
    __syncthreads();
    const float s = ws[8];
    float4 y; y.x = v.x * s; y.y = v.y * s; y.z = v.z * s; y.w = v.w * s;
    ((float4*)(g_Xn + (size_t)row * DIMK))[tid] = y;

    __half2 h0 = __floats2half2_rn(y.x, y.y);
    __half2 h1 = __floats2half2_rn(y.z, y.w);
    uint2 u;
    u.x = *(const uint32_t*)&h0;
    u.y = *(const uint32_t*)&h1;
    *(uint2*)(g_Xh + (size_t)row * DIMK + tid * 4) = u;
}

// ---------------- kernel 2: persistent fp16 GEMM over the block triangle ----------------
// 444 CTAs (3/SM); CTA c runs jobs c, c+444, ... Tile = 128 rows x 128 cols.
// 8 warps in 2(m) x 4(n): warp tile 64x32. Stage = K-chunk 64:
// A 128x64 (16KB) + B 128x64 (16KB) = 32KB/buffer, 2 buffers, depth 1,
// one __syncthreads per stage. Row-side AND column-side folds into g_best.

__device__ __forceinline__ void copy_stream(uint32_t sbase, const uint32_t* jtab,
                                            int s, int S, int tid) {
    if (s < S) {
        const uint32_t rbcb = jtab[s >> 4];
        const int rb = (int)(rbcb >> 8), cb = (int)(rbcb & 255u), kc = s & 15;
        const uint32_t dst = sbase + (uint32_t)(s & 1) * STAGE_BYTES;
        const __half* gA = g_Xh + (size_t)(rb * 128) * DIMK + kc * 64;
        const __half* gB = g_Xh + (size_t)(cb * 128) * DIMK + kc * 64;
        #pragma unroll
        for (int i = 0; i < 4; i++) {
            const int idx = tid + i * 256;
            const int r = idx >> 3, ch = idx & 7;
            const uint32_t doff = (uint32_t)r * 128u + ((uint32_t)(ch ^ (r & 7)) << 4);
            cp16(dst + doff, gA + (size_t)r * DIMK + ch * 8);
        }
        #pragma unroll
        for (int i = 0; i < 4; i++) {
            const int idx = tid + i * 256;
            const int r = idx >> 3, ch = idx & 7;
            const uint32_t doff = (uint32_t)r * 128u + ((uint32_t)(ch ^ (r & 7)) << 4);
            cp16(dst + 16384u + doff, gB + (size_t)r * DIMK + ch * 8);
        }
    }
    asm volatile("cp.async.commit_group;" ::: "memory");
}

__global__ void __launch_bounds__(256, 3) koleo_argmax_kernel() {
    extern __shared__ unsigned char smem[];
    const uint32_t sbase = smem_u32(smem);
    uint32_t* jtab = (uint32_t*)(smem + 2 * STAGE_BYTES);
    const int tid = threadIdx.x;
    const int lane = tid & 31;
    const int wid = tid >> 5;
    const int wm = wid & 1;        // rows [wm*64, wm*64+64)
    const int wn = wid >> 1;       // cols [wn*32, wn*32+32)
    const int cta = blockIdx.x;
    const int m = (NJOBS_T - cta + NCTA3 - 1) / NCTA3;   // jobs for this CTA (<=5)
    const int S = m * 16;

    if (tid < 8 && tid < m) jtab[tid] = job_decode(cta + tid * NCTA3);
    __syncthreads();

    uint32_t c2[4][4][2];   // fp16x2 accumulators (warp tile 64x32)
    #pragma unroll
    for (int a = 0; a < 4; a++)
        #pragma unroll
        for (int b = 0; b < 4; b++) { c2[a][b][0] = 0u; c2[a][b][1] = 0u; }

    copy_stream(sbase, jtab, 0, S, tid);

    for (int s = 0; s < S; s++) {
        asm volatile("cp.async.wait_group 0;" ::: "memory");
        __syncthreads();
        copy_stream(sbase, jtab, s + 1, S, tid);   // overlaps compute(s)

        const uint32_t A = sbase + (uint32_t)(s & 1) * STAGE_BYTES;
        const uint32_t B = A + 16384u;

        #pragma unroll
        for (int t = 0; t < 4; t++) {
            const uint32_t kc = (uint32_t)(t << 1) + (uint32_t)(lane >> 4);
            uint32_t bf[2][4], af[4][4];
            #pragma unroll
            for (int nb = 0; nb < 2; nb++) {
                const uint32_t r = (uint32_t)(wn * 32 + nb * 16 + (lane & 15));
                const uint32_t addr = B + r * 128u + ((kc ^ (r & 7u)) << 4);
                ldsm4(bf[nb][0], bf[nb][1], bf[nb][2], bf[nb][3], addr);
            }
            #pragma unroll
            for (int mt = 0; mt < 4; mt++) {
                const uint32_t r = (uint32_t)(wm * 64 + mt * 16 + (lane & 15));
                const uint32_t addr = A + r * 128u + ((kc ^ (r & 7u)) << 4);
                ldsm4(af[mt][0], af[mt][1], af[mt][2], af[mt][3], addr);
            }
            #pragma unroll
            for (int mt = 0; mt < 4; mt++)
                #pragma unroll
                for (int j = 0; j < 4; j++)
                    mma16816h(c2[mt][j], af[mt][0], af[mt][1], af[mt][2], af[mt][3],
                              bf[j >> 1][j & 1], bf[j >> 1][2 + (j & 1)]);
        }

        if ((s & 15) == 15) {
            const uint32_t rbcb = jtab[s >> 4];
            const int rb = (int)(rbcb >> 8), cb = (int)(rbcb & 255u);
            const int colb = cb * 128 + wn * 32;
            const int rowb = rb * 128 + wm * 64;

            // ---- column-side fold (symmetry): per-column max over 128 rows ----
            #pragma unroll
            for (int j = 0; j < 4; j++) {
                #pragma unroll
                for (int h = 0; h < 2; h++) {
                    const int gcol = colb + j * 8 + (lane & 3) * 2 + h;
                    float cv = -2.f; int cr = 0;
                    #pragma unroll
                    for (int mt = 0; mt < 4; mt++) {
                        #pragma unroll
                        for (int rh = 0; rh < 2; rh++) {
                            const __half2 hv = *(const __half2*)&c2[mt][j][rh];
                            const float v = h ? __high2float(hv) : __low2float(hv);
                            const int grow = rowb + mt * 16 + (lane >> 2) + rh * 8;
                            if (grow != gcol && (v > cv || (v == cv && grow < cr))) {
                                cv = v; cr = grow;
                            }
                        }
                    }
                    unsigned long long key =
                        ((unsigned long long)fenc(cv) << 32) |
                        (unsigned long long)(0xFFFFFFFFu - (uint32_t)cr);
                    #pragma unroll
                    for (int o = 4; o <= 16; o <<= 1) {
                        const unsigned long long ok = __shfl_xor_sync(0xFFFFFFFFu, key, o);
                        if (ok > key) key = ok;
                    }
                    if (lane < 4) atomicMax(&g_best[gcol], key);
                }
            }

            // ---- row-side fold + accumulator reset ----
            #pragma unroll
            for (int mt = 0; mt < 4; mt++) {
                #pragma unroll
                for (int rh = 0; rh < 2; rh++) {
                    const int grow = rowb + mt * 16 + (lane >> 2) + rh * 8;
                    float bv = -2.f; int bi = 0;
                    #pragma unroll
                    for (int j = 0; j < 4; j++) {
                        const __half2 hv = *(const __half2*)&c2[mt][j][rh];
                        const float v0 = __low2float(hv);
                        const float v1 = __high2float(hv);
                        const int col0 = colb + j * 8 + (lane & 3) * 2;
                        if (col0 != grow && v0 > bv) { bv = v0; bi = col0; }
                        if (col0 + 1 != grow && v1 > bv) { bv = v1; bi = col0 + 1; }
                        c2[mt][j][rh] = 0u;
                    }
                    unsigned long long key =
                        ((unsigned long long)fenc(bv) << 32) |
                        (unsigned long long)(0xFFFFFFFFu - (uint32_t)bi);
                    #pragma unroll
                    for (int o = 1; o <= 2; o <<= 1) {
                        const unsigned long long ok = __shfl_xor_sync(0xFFFFFFFFu, key, o);
                        if (ok > key) key = ok;
                    }
                    if ((lane & 3) == 0) atomicMax(&g_best[grow], key);
                }
            }
        }
    }
}

// ---------------- kernel 3: exact fp32 distance to argmax neighbor ----------------
__global__ void koleo_dist_kernel() {
    const int i = blockIdx.x;
    const int tid = threadIdx.x;  // 128
    const int j = (int)(0xFFFFFFFFu - (uint32_t)g_best[i]);
    const float4* a = (const float4*)(g_Xn + (size_t)i * DIMK);
    const float4* b = (const float4*)(g_Xn + (size_t)j * DIMK);
    float s = 0.f;
    #pragma unroll
    for (int t = 0; t < 2; t++) {
        const int idx = tid + t * 128;
        const float4 av = a[idx], bv = b[idx];
        const float d0 = av.x - bv.x + 1e-8f;
        const float d1 = av.y - bv.y + 1e-8f;
        const float d2 = av.z - bv.z + 1e-8f;
        const float d3 = av.w - bv.w + 1e-8f;
        s += d0 * d0 + d1 * d1 + d2 * d2 + d3 * d3;
    }
    #pragma unroll
    for (int o = 16; o; o >>= 1) s += __shfl_xor_sync(0xFFFFFFFFu, s, o);
    __shared__ float ws[4];
    if ((tid & 31) == 0) ws[tid >> 5] = s;
    __syncthreads();
    if (tid == 0) {
        const float t = ws[0] + ws[1] + ws[2] + ws[3];
        g_logd[i] = logf(sqrtf(t) + 1e-8f);
    }
}

// ---------------- kernel 4: deterministic mean reduction ----------------
__global__ void koleo_finish_kernel(float* __restrict__ out) {
    const int tid = threadIdx.x;  // 1024
    float s = 0.f;
    #pragma unroll
    for (int t = 0; t < 8; t++) s += g_logd[tid + t * 1024];
    #pragma unroll
    for (int o = 16; o; o >>= 1) s += __shfl_xor_sync(0xFFFFFFFFu, s, o);
    __shared__ float ws[32];
    if ((tid & 31) == 0) ws[tid >> 5] = s;
    __syncthreads();
    if (tid == 0) {
        float t = 0.f;
        #pragma unroll
        for (int i = 0; i < 32; i++) t += ws[i];
        out[0] = -(t / 8192.f);
    }
}

// ---------------- launch ----------------
extern "C" void kernel_launch(void* const* d_in, const int* in_sizes, int n_in,
                              void* d_out, int out_size) {
    (void)in_sizes; (void)n_in; (void)out_size;
    const float* x = (const float*)d_in[0];
    const int smem_bytes = 2 * 32768 + 64;
    cudaFuncSetAttribute(koleo_argmax_kernel, cudaFuncAttributeMaxDynamicSharedMemorySize,
                         smem_bytes);
    koleo_normalize_kernel<<<N_ROWS, 256>>>(x);
    koleo_argmax_kernel<<<NCTA3, 256, smem_bytes>>>();
    koleo_dist_kernel<<<N_ROWS, 128>>>();
    koleo_finish_kernel<<<1, 1024>>>((float*)d_out);
}